// round 1
// baseline (speedup 1.0000x reference)
#include <cuda_runtime.h>

#define NF 39
#define NV 200000
#define NE 16
#define ND 32
#define NB 16384
#define RPB 128            // rows per block
#define NT 256             // threads per block (2 threads per row: d-halves)

// ---------- f32x2 packed helpers (sm_103a FFMA2 path, PTX-only) ----------
static __device__ __forceinline__ unsigned long long pack2(float a, float b) {
    unsigned long long r;
    asm("mov.b64 %0, {%1, %2};" : "=l"(r) : "f"(a), "f"(b));
    return r;
}
static __device__ __forceinline__ unsigned long long splat2(float a) {
    unsigned long long r;
    asm("mov.b64 %0, {%1, %1};" : "=l"(r) : "f"(a));
    return r;
}
static __device__ __forceinline__ void ffma2(unsigned long long& acc,
                                             unsigned long long a,
                                             unsigned long long b) {
    asm("fma.rn.f32x2 %0, %1, %2, %0;" : "+l"(acc) : "l"(a), "l"(b));
}
static __device__ __forceinline__ void unpack2(unsigned long long v, float& lo, float& hi) {
    asm("mov.b64 {%0, %1}, %2;" : "=f"(lo), "=f"(hi) : "l"(v));
}

// ---------- smem layout (bytes) ----------
// Wp   : 39*32*16 packed (W1,Wi) pairs, 8B each = 159744
// mlp  : lin1_w[1024] lin2_w[1024] lin1_b@2048 lin2_b@2080 last_w@2112 last_b@2144 (pad to 2176 floats)
// xbuf : 128 rows * 33 floats (pad for conflict-free)
// ybuf : same
#define W_PAIRS   (NF * ND * NE)
#define OFF_MLP   (W_PAIRS * 8)
#define MLP_FLOATS 2176
#define OFF_X     (OFF_MLP + MLP_FLOATS * 4)
#define XB_FLOATS (RPB * 33)
#define OFF_Y     (OFF_X + XB_FLOATS * 4)
#define SMEM_TOTAL (OFF_Y + XB_FLOATS * 4)   // 202240 bytes

extern __shared__ unsigned char smem_raw[];

__global__ void __launch_bounds__(NT, 1)
pnn_kernel(const int* __restrict__ Xi, const float* __restrict__ Xv,
           const float* __restrict__ tables,
           const float* __restrict__ W1, const float* __restrict__ Wi,
           const float* __restrict__ l1w, const float* __restrict__ l1b,
           const float* __restrict__ l2w, const float* __restrict__ l2b,
           const float* __restrict__ lw, const float* __restrict__ lb,
           float* __restrict__ out)
{
    unsigned long long* Wp = reinterpret_cast<unsigned long long*>(smem_raw);
    float* mlp  = reinterpret_cast<float*>(smem_raw + OFF_MLP);
    float* xbuf = reinterpret_cast<float*>(smem_raw + OFF_X);
    float* ybuf = reinterpret_cast<float*>(smem_raw + OFF_Y);

    const int tid = threadIdx.x;

    // ---- stage packed weights: Wp[(f*32 + d)*16 + e] = {W1[d,f,e], Wi[d,f,e]} ----
    for (int i = tid; i < W_PAIRS; i += NT) {
        int f = i >> 9;            // i / 512
        int r = i & 511;
        int d = r >> 4;
        int e = r & 15;
        int g = d * (NF * NE) + f * NE + e;
        Wp[i] = pack2(W1[g], Wi[g]);
    }
    // ---- stage MLP weights ----
    for (int i = tid; i < 1024; i += NT) { mlp[i] = l1w[i]; mlp[1024 + i] = l2w[i]; }
    if (tid < 32) {
        mlp[2048 + tid] = l1b[tid];
        mlp[2080 + tid] = l2b[tid];
        mlp[2112 + tid] = lw[tid];
        if (tid == 0) mlp[2144] = lb[0];
    }
    __syncthreads();

    const int h  = tid >> 7;       // d-half: 0 or 1 (warps are h-uniform)
    const int r  = tid & 127;      // local row
    const int row = blockIdx.x * RPB + r;

    const int*   xi = Xi + row * NF;
    const float* xv = Xv + row * NF;

    unsigned long long acc[16];
#pragma unroll
    for (int d = 0; d < 16; d++) acc[d] = 0ull;

    // preload field 0's table row
    int   idx0 = xi[0];
    float vcur = xv[0];
    const float4* tp = reinterpret_cast<const float4*>(tables + (long)idx0 * NE);
    float4 t0 = tp[0], t1 = tp[1], t2 = tp[2], t3 = tp[3];

    for (int f = 0; f < NF; f++) {
        // prefetch next field's row (double buffer; hides ~577cyc DRAM behind 256 FFMA2)
        int   fn = (f + 1 < NF) ? (f + 1) : (NF - 1);
        int   idn = xi[fn];
        float vnext = xv[fn];
        const float4* tq = reinterpret_cast<const float4*>(
            tables + ((long)fn * NV + (long)idn) * NE);
        float4 n0 = tq[0], n1 = tq[1], n2 = tq[2], n3 = tq[3];

        // emb values splatted to both f32x2 lanes
        unsigned long long emb2[16];
        emb2[0]  = splat2(t0.x * vcur); emb2[1]  = splat2(t0.y * vcur);
        emb2[2]  = splat2(t0.z * vcur); emb2[3]  = splat2(t0.w * vcur);
        emb2[4]  = splat2(t1.x * vcur); emb2[5]  = splat2(t1.y * vcur);
        emb2[6]  = splat2(t1.z * vcur); emb2[7]  = splat2(t1.w * vcur);
        emb2[8]  = splat2(t2.x * vcur); emb2[9]  = splat2(t2.y * vcur);
        emb2[10] = splat2(t2.z * vcur); emb2[11] = splat2(t2.w * vcur);
        emb2[12] = splat2(t3.x * vcur); emb2[13] = splat2(t3.y * vcur);
        emb2[14] = splat2(t3.z * vcur); emb2[15] = splat2(t3.w * vcur);

        // this thread's 16 d's: one FFMA2 per (d,e) covers BOTH W1 and Wi
        const unsigned long long* wbase = Wp + (f * ND + h * 16) * NE;
#pragma unroll
        for (int d = 0; d < 16; d++) {
            const ulonglong2* w2 = reinterpret_cast<const ulonglong2*>(wbase + d * NE);
#pragma unroll
            for (int e = 0; e < 8; e++) {
                ulonglong2 w = w2[e];          // LDS.128, warp-broadcast address
                ffma2(acc[d], emb2[2 * e],     w.x);
                ffma2(acc[d], emb2[2 * e + 1], w.y);
            }
        }

        t0 = n0; t1 = n1; t2 = n2; t3 = n3;
        vcur = vnext;
    }

    // x[d] = first_order[d] + s[d]^2
#pragma unroll
    for (int d = 0; d < 16; d++) {
        float fo, s;
        unpack2(acc[d], fo, s);
        xbuf[r * 33 + h * 16 + d] = fmaf(s, s, fo);
    }
    __syncthreads();

    // layer 1: y = relu(x @ l1w^T + b1); thread computes its 16 outputs
#pragma unroll
    for (int j = 0; j < 16; j++) {
        int jj = h * 16 + j;
        float s = mlp[2048 + jj];
        const float* wrow = mlp + jj * 32;
        const float* xr = xbuf + r * 33;
#pragma unroll
        for (int k = 0; k < 32; k++) s = fmaf(xr[k], wrow[k], s);
        ybuf[r * 33 + jj] = fmaxf(s, 0.0f);
    }
    __syncthreads();

    // layer 2: z = relu(y @ l2w^T + b2) -> back into xbuf
#pragma unroll
    for (int j = 0; j < 16; j++) {
        int jj = h * 16 + j;
        float s = mlp[2080 + jj];
        const float* wrow = mlp + 1024 + jj * 32;
        const float* yr = ybuf + r * 33;
#pragma unroll
        for (int k = 0; k < 32; k++) s = fmaf(yr[k], wrow[k], s);
        xbuf[r * 33 + jj] = fmaxf(s, 0.0f);
    }
    __syncthreads();

    // final: out = z @ last_w^T + last_b (scalar)
    if (h == 0) {
        float s = mlp[2144];
        const float* zr = xbuf + r * 33;
#pragma unroll
        for (int k = 0; k < 32; k++) s = fmaf(zr[k], mlp[2112 + k], s);
        out[row] = s;
    }
}

extern "C" void kernel_launch(void* const* d_in, const int* in_sizes, int n_in,
                              void* d_out, int out_size)
{
    const int*   Xi     = (const int*)  d_in[0];
    const float* Xv     = (const float*)d_in[1];
    const float* tables = (const float*)d_in[2];
    const float* W1     = (const float*)d_in[3];
    const float* Wi     = (const float*)d_in[4];
    const float* l1w    = (const float*)d_in[5];
    const float* l1b    = (const float*)d_in[6];
    const float* l2w    = (const float*)d_in[7];
    const float* l2b    = (const float*)d_in[8];
    const float* lw     = (const float*)d_in[9];
    const float* lb     = (const float*)d_in[10];

    cudaFuncSetAttribute(pnn_kernel, cudaFuncAttributeMaxDynamicSharedMemorySize, SMEM_TOTAL);

    pnn_kernel<<<NB / RPB, NT, SMEM_TOTAL>>>(
        Xi, Xv, tables, W1, Wi, l1w, l1b, l2w, l2b, lw, lb, (float*)d_out);
}